// round 1
// baseline (speedup 1.0000x reference)
#include <cuda_runtime.h>

#define N_NODES 50000
#define N_EDGES 1600000
#define IN_DIM 128
#define HID 64
#define NUM_LAYERS 3
#define LN_EPS 1e-5f
#define NCHUNK ((N_NODES + 511) / 512)

// ---------------- scratch (device globals; no runtime allocation) ----------
__device__ float g_hA[N_NODES * HID];
__device__ float g_hB[N_NODES * HID];
__device__ float g_agg[N_NODES * HID];
__device__ int   g_cnt[N_NODES];
__device__ int   g_excl[N_NODES];
__device__ int   g_row[N_NODES];
__device__ int   g_cur[N_NODES];
__device__ int   g_csum[128];
__device__ float g_invdeg[N_NODES];
__device__ int   g_esrc[N_EDGES];

__device__ __forceinline__ float* selbuf(int s) { return s == 0 ? g_hA : g_hB; }

// ---------------- CSR construction -----------------------------------------
__global__ void k_zero_cnt() {
    int i = blockIdx.x * blockDim.x + threadIdx.x;
    if (i < N_NODES) g_cnt[i] = 0;
}

__global__ void k_count(const int* __restrict__ dst) {
    int e = blockIdx.x * blockDim.x + threadIdx.x;
    if (e < N_EDGES) atomicAdd(&g_cnt[dst[e]], 1);
}

__global__ void k_scan1() {
    __shared__ int s[512];
    int c = blockIdx.x, t = threadIdx.x, i = c * 512 + t;
    int v = (i < N_NODES) ? g_cnt[i] : 0;
    s[t] = v;
    __syncthreads();
    for (int off = 1; off < 512; off <<= 1) {
        int x = (t >= off) ? s[t - off] : 0;
        __syncthreads();
        s[t] += x;
        __syncthreads();
    }
    if (i < N_NODES) g_excl[i] = s[t] - v;
    if (t == 511) g_csum[c] = s[511];
}

__global__ void k_scan2() {
    __shared__ int s[128];
    int t = threadIdx.x;
    int v = (t < NCHUNK) ? g_csum[t] : 0;
    s[t] = v;
    __syncthreads();
    for (int off = 1; off < 128; off <<= 1) {
        int x = (t >= off) ? s[t - off] : 0;
        __syncthreads();
        s[t] += x;
        __syncthreads();
    }
    if (t < NCHUNK) g_csum[t] = s[t] - v;
}

__global__ void k_scan3() {
    int i = blockIdx.x * blockDim.x + threadIdx.x;
    if (i < N_NODES) {
        int r = g_excl[i] + g_csum[i >> 9];
        g_row[i] = r;
        g_cur[i] = r;
        int c = g_cnt[i];
        g_invdeg[i] = 1.0f / (float)(c > 0 ? c : 1);
    }
}

__global__ void k_scatter(const int* __restrict__ src, const int* __restrict__ dst) {
    int e = blockIdx.x * blockDim.x + threadIdx.x;
    if (e < N_EDGES) {
        int p = atomicAdd(&g_cur[dst[e]], 1);
        g_esrc[p] = src[e];
    }
}

// ---------------- fc projection: h0 = relu(x @ W^T + b) --------------------
__global__ void k_fc(const float* __restrict__ x, const float* __restrict__ W,
                     const float* __restrict__ b) {
    __shared__ float sA[32 * IN_DIM];
    int t = threadIdx.x;
    int nb = blockIdx.x * 32;
    for (int i = t; i < 32 * (IN_DIM / 4); i += 256) {
        int n = i >> 5, k4 = i & 31;
        float4 v = make_float4(0.f, 0.f, 0.f, 0.f);
        if (nb + n < N_NODES)
            v = ((const float4*)x)[(size_t)(nb + n) * (IN_DIM / 4) + k4];
        ((float4*)sA)[i] = v;
    }
    __syncthreads();
    int j = t & 63, g = t >> 6;  // 4 groups x 8 nodes
    const float* Wj = W + j * IN_DIM;
    float acc[8];
#pragma unroll
    for (int n = 0; n < 8; n++) acc[n] = 0.f;
#pragma unroll 8
    for (int k = 0; k < IN_DIM; k += 4) {
        float4 w = __ldg((const float4*)(Wj + k));
#pragma unroll
        for (int n = 0; n < 8; n++) {
            float4 a = *(const float4*)&sA[(g * 8 + n) * IN_DIM + k];
            acc[n] = fmaf(a.x, w.x, fmaf(a.y, w.y, fmaf(a.z, w.z, fmaf(a.w, w.w, acc[n]))));
        }
    }
    float bj = __ldg(&b[j]);
#pragma unroll
    for (int n = 0; n < 8; n++) {
        int gn = nb + g * 8 + n;
        if (gn < N_NODES) g_hA[(size_t)gn * HID + j] = fmaxf(acc[n] + bj, 0.f);
    }
}

// ---------------- mean aggregation over CSR (warp per dst node) ------------
__global__ void k_aggregate(int hin_sel) {
    int gw = (blockIdx.x * blockDim.x + threadIdx.x) >> 5;
    if (gw >= N_NODES) return;
    int lane = threadIdx.x & 31;
    const float2* hp = (const float2*)selbuf(hin_sel);
    int s = g_row[gw], c = g_cnt[gw];
    float ax = 0.f, ay = 0.f;
    int e = 0;
    for (; e + 4 <= c; e += 4) {
        int s0 = g_esrc[s + e + 0];
        int s1 = g_esrc[s + e + 1];
        int s2 = g_esrc[s + e + 2];
        int s3 = g_esrc[s + e + 3];
        float2 v0 = hp[(size_t)s0 * 32 + lane];
        float2 v1 = hp[(size_t)s1 * 32 + lane];
        float2 v2 = hp[(size_t)s2 * 32 + lane];
        float2 v3 = hp[(size_t)s3 * 32 + lane];
        ax += (v0.x + v1.x) + (v2.x + v3.x);
        ay += (v0.y + v1.y) + (v2.y + v3.y);
    }
    for (; e < c; e++) {
        int s0 = g_esrc[s + e];
        float2 v0 = hp[(size_t)s0 * 32 + lane];
        ax += v0.x;
        ay += v0.y;
    }
    float id = g_invdeg[gw];
    ((float2*)g_agg)[(size_t)gw * 32 + lane] = make_float2(ax * id, ay * id);
}

// ---------------- layer: h_new = agg@Wl^T + h@Wr^T + b (+LN+ReLU) ----------
__global__ void k_layer(int hin_sel, int layer, int doLN, float* out_ext, int hout_sel,
                        const float* __restrict__ lin_l, const float* __restrict__ lin_r,
                        const float* __restrict__ lin_b, const float* __restrict__ ln_g,
                        const float* __restrict__ ln_b) {
    __shared__ float sA[32 * HID];
    __shared__ float sH[32 * HID];
    int t = threadIdx.x;
    int nb = blockIdx.x * 32;
    const float* hin = selbuf(hin_sel);
    for (int i = t; i < 32 * (HID / 4); i += 256) {
        int n = i >> 4, k4 = i & 15;
        float4 va = make_float4(0.f, 0.f, 0.f, 0.f), vh = va;
        if (nb + n < N_NODES) {
            va = ((const float4*)g_agg)[(size_t)(nb + n) * (HID / 4) + k4];
            vh = ((const float4*)hin)[(size_t)(nb + n) * (HID / 4) + k4];
        }
        ((float4*)sA)[i] = va;
        ((float4*)sH)[i] = vh;
    }
    __syncthreads();
    int j = t & 63, g = t >> 6;  // 4 groups x 8 nodes
    const float* Wl = lin_l + layer * HID * HID + j * HID;
    const float* Wr = lin_r + layer * HID * HID + j * HID;
    float acc[8];
#pragma unroll
    for (int n = 0; n < 8; n++) acc[n] = 0.f;
#pragma unroll 4
    for (int k = 0; k < HID; k += 4) {
        float4 wl = __ldg((const float4*)(Wl + k));
        float4 wr = __ldg((const float4*)(Wr + k));
#pragma unroll
        for (int n = 0; n < 8; n++) {
            const float4 a = *(const float4*)&sA[(g * 8 + n) * HID + k];
            const float4 hh = *(const float4*)&sH[(g * 8 + n) * HID + k];
            acc[n] = fmaf(a.x, wl.x, fmaf(a.y, wl.y, fmaf(a.z, wl.z, fmaf(a.w, wl.w,
                     fmaf(hh.x, wr.x, fmaf(hh.y, wr.y, fmaf(hh.z, wr.z, fmaf(hh.w, wr.w, acc[n]))))))));
        }
    }
    float bj = __ldg(&lin_b[layer * HID + j]);
    __syncthreads();  // done reading sA tiles
#pragma unroll
    for (int n = 0; n < 8; n++) sA[(g * 8 + n) * HID + j] = acc[n] + bj;
    __syncthreads();

    float* hout = out_ext ? out_ext : selbuf(hout_sel);
    int w = t >> 5, lane = t & 31;
    int lnl = doLN ? layer : 0;  // keep pointer math in-bounds
    const float* lg = ln_g + lnl * HID;
    const float* lb = ln_b + lnl * HID;
    for (int n = w * 4; n < w * 4 + 4; n++) {
        int gn = nb + n;
        if (gn >= N_NODES) continue;  // uniform across warp
        float2 v = *(float2*)&sA[n * HID + lane * 2];
        if (doLN) {
            float s = v.x + v.y;
            float sq = v.x * v.x + v.y * v.y;
#pragma unroll
            for (int off = 16; off; off >>= 1) {
                s += __shfl_xor_sync(0xffffffffu, s, off);
                sq += __shfl_xor_sync(0xffffffffu, sq, off);
            }
            float mu = s * (1.0f / HID);
            float var = sq * (1.0f / HID) - mu * mu;
            float r = rsqrtf(var + LN_EPS);
            float y0 = fmaxf(fmaf(__ldg(&lg[lane * 2 + 0]), (v.x - mu) * r, __ldg(&lb[lane * 2 + 0])), 0.f);
            float y1 = fmaxf(fmaf(__ldg(&lg[lane * 2 + 1]), (v.y - mu) * r, __ldg(&lb[lane * 2 + 1])), 0.f);
            v = make_float2(y0, y1);
        }
        ((float2*)hout)[(size_t)gn * 32 + lane] = v;
    }
}

// ---------------- launcher --------------------------------------------------
extern "C" void kernel_launch(void* const* d_in, const int* in_sizes, int n_in,
                              void* d_out, int out_size) {
    const float* x     = (const float*)d_in[0];
    const int*   ei    = (const int*)d_in[1];
    // d_in[2] = batch (unused by reference output)
    const float* fcW   = (const float*)d_in[3];
    const float* fcb   = (const float*)d_in[4];
    const float* lin_l = (const float*)d_in[5];
    const float* lin_r = (const float*)d_in[6];
    const float* lin_b = (const float*)d_in[7];
    const float* ln_g  = (const float*)d_in[8];
    const float* ln_b  = (const float*)d_in[9];
    const int* src = ei;
    const int* dst = ei + N_EDGES;

    k_zero_cnt<<<(N_NODES + 255) / 256, 256>>>();
    k_count<<<(N_EDGES + 255) / 256, 256>>>(dst);
    k_scan1<<<NCHUNK, 512>>>();
    k_scan2<<<1, 128>>>();
    k_scan3<<<(N_NODES + 255) / 256, 256>>>();
    k_scatter<<<(N_EDGES + 255) / 256, 256>>>(src, dst);

    k_fc<<<(N_NODES + 31) / 32, 256>>>(x, fcW, fcb);

    int cur = 0;
    for (int l = 0; l < NUM_LAYERS; l++) {
        k_aggregate<<<(N_NODES * 32 + 255) / 256, 256>>>(cur);
        int doLN = (l < NUM_LAYERS - 1) ? 1 : 0;
        float* out_ext = (l == NUM_LAYERS - 1) ? (float*)d_out : nullptr;
        k_layer<<<(N_NODES + 31) / 32, 256>>>(cur, l, doLN, out_ext, 1 - cur,
                                              lin_l, lin_r, lin_b, ln_g, ln_b);
        cur = 1 - cur;
    }
}

// round 2
// speedup vs baseline: 1.5880x; 1.5880x over previous
#include <cuda_runtime.h>
#include <cuda_fp16.h>

#define N_NODES 50000
#define N_EDGES 1600000
#define IN_DIM 128
#define HID 64
#define NUM_LAYERS 3
#define LN_EPS 1e-5f
#define NCHUNK ((N_NODES + 511) / 512)

// GEMM tiling: 128 nodes x 64 outputs per block, 256 threads, thread tile 4n x 8j
#define GB_NODES 128
#define RES_PAD 68
#define GEMM_SMEM (( (128*128) + (128*64) ) * 4)   // sAT + sWT bytes = 98304

// ---------------- scratch (device globals) ----------------------------------
__device__ float  g_h32A[N_NODES * HID];
__device__ float  g_h32B[N_NODES * HID];
__device__ __half g_h16A[N_NODES * HID];
__device__ __half g_h16B[N_NODES * HID];
__device__ float  g_agg[N_NODES * HID];
__device__ int    g_cnt[N_NODES];
__device__ int    g_excl[N_NODES];
__device__ int    g_row[N_NODES];
__device__ int    g_cur[N_NODES];
__device__ int    g_csum[128];
__device__ float  g_invdeg[N_NODES];
__device__ int    g_esrc[N_EDGES];

__device__ __forceinline__ float*  h32buf(int s) { return s == 0 ? g_h32A : g_h32B; }
__device__ __forceinline__ __half* h16buf(int s) { return s == 0 ? g_h16A : g_h16B; }

// ---------------- CSR construction -------------------------------------------
__global__ void k_zero_cnt() {
    int i = blockIdx.x * blockDim.x + threadIdx.x;
    if (i < N_NODES) g_cnt[i] = 0;
}

__global__ void k_count(const int* __restrict__ dst) {
    int e = blockIdx.x * blockDim.x + threadIdx.x;
    if (e < N_EDGES) atomicAdd(&g_cnt[dst[e]], 1);
}

__global__ void k_scan1() {
    __shared__ int s[512];
    int c = blockIdx.x, t = threadIdx.x, i = c * 512 + t;
    int v = (i < N_NODES) ? g_cnt[i] : 0;
    s[t] = v;
    __syncthreads();
    for (int off = 1; off < 512; off <<= 1) {
        int x = (t >= off) ? s[t - off] : 0;
        __syncthreads();
        s[t] += x;
        __syncthreads();
    }
    if (i < N_NODES) g_excl[i] = s[t] - v;
    if (t == 511) g_csum[c] = s[511];
}

__global__ void k_scan2() {
    __shared__ int s[128];
    int t = threadIdx.x;
    int v = (t < NCHUNK) ? g_csum[t] : 0;
    s[t] = v;
    __syncthreads();
    for (int off = 1; off < 128; off <<= 1) {
        int x = (t >= off) ? s[t - off] : 0;
        __syncthreads();
        s[t] += x;
        __syncthreads();
    }
    if (t < NCHUNK) g_csum[t] = s[t] - v;
}

__global__ void k_scan3() {
    int i = blockIdx.x * blockDim.x + threadIdx.x;
    if (i < N_NODES) {
        int r = g_excl[i] + g_csum[i >> 9];
        g_row[i] = r;
        g_cur[i] = r;
        int c = g_cnt[i];
        g_invdeg[i] = 1.0f / (float)(c > 0 ? c : 1);
    }
}

__global__ void k_scatter(const int* __restrict__ src, const int* __restrict__ dst) {
    int e = blockIdx.x * blockDim.x + threadIdx.x;
    if (e < N_EDGES) {
        int p = atomicAdd(&g_cur[dst[e]], 1);
        g_esrc[p] = src[e];
    }
}

// ---------------- mean aggregation over CSR (warp per dst node, fp16 gather) -
__global__ void k_aggregate(int hsel) {
    int gw = (blockIdx.x * blockDim.x + threadIdx.x) >> 5;
    if (gw >= N_NODES) return;
    int lane = threadIdx.x & 31;
    const __half2* hp = (const __half2*)h16buf(hsel);
    int s = g_row[gw], c = g_cnt[gw];
    float ax = 0.f, ay = 0.f;
    int e = 0;
    for (; e + 4 <= c; e += 4) {
        int s0 = g_esrc[s + e + 0];
        int s1 = g_esrc[s + e + 1];
        int s2 = g_esrc[s + e + 2];
        int s3 = g_esrc[s + e + 3];
        float2 v0 = __half22float2(hp[(size_t)s0 * 32 + lane]);
        float2 v1 = __half22float2(hp[(size_t)s1 * 32 + lane]);
        float2 v2 = __half22float2(hp[(size_t)s2 * 32 + lane]);
        float2 v3 = __half22float2(hp[(size_t)s3 * 32 + lane]);
        ax += (v0.x + v1.x) + (v2.x + v3.x);
        ay += (v0.y + v1.y) + (v2.y + v3.y);
    }
    for (; e < c; e++) {
        float2 v0 = __half22float2(hp[(size_t)g_esrc[s + e] * 32 + lane]);
        ax += v0.x;
        ay += v0.y;
    }
    float id = g_invdeg[gw];
    ((float2*)g_agg)[(size_t)gw * 32 + lane] = make_float2(ax * id, ay * id);
}

// ---------------- register-blocked GEMM: out[n][64] = A[n][128] @ W[64][128]^T
// xA0 != null : A = xA0 (K=128 contiguous), W0 = [64][128]          (fc path)
// xA0 == null : A = [g_agg | h32(hsel)],    W = [W0 | W1] ([64][64] each)
// mode: 0 = ReLU, 1 = LayerNorm+ReLU, 2 = plain (write outF only)
__global__ void k_gemm(const float* __restrict__ xA0, int hsel,
                       const float* __restrict__ W0, const float* __restrict__ W1,
                       const float* __restrict__ bias,
                       const float* __restrict__ lng, const float* __restrict__ lnbeta,
                       int mode, int outsel, float* __restrict__ outF) {
    extern __shared__ float sm[];
    float* sAT = sm;               // [128 k][128 n]
    float* sWT = sm + 128 * 128;   // [128 k][64 j]
    float* sRes = sm;              // reuse: [128 n][RES_PAD]

    int t = threadIdx.x;
    int nb = blockIdx.x * GB_NODES;

    // ---- load A tile, transposed ----
    const float* h32 = h32buf(hsel);
#pragma unroll
    for (int it = 0; it < 16; it++) {
        int idx = it * 256 + t;
        int n = idx & 127, k4 = idx >> 7;   // k4: 0..31
        int gn = nb + n;
        float4 v = make_float4(0.f, 0.f, 0.f, 0.f);
        if (gn < N_NODES) {
            if (xA0) v = ((const float4*)xA0)[(size_t)gn * 32 + k4];
            else     v = (k4 < 16) ? ((const float4*)g_agg)[(size_t)gn * 16 + k4]
                                   : ((const float4*)h32)[(size_t)gn * 16 + (k4 - 16)];
        }
        int k = k4 * 4;
        sAT[(k + 0) * 128 + n] = v.x;
        sAT[(k + 1) * 128 + n] = v.y;
        sAT[(k + 2) * 128 + n] = v.z;
        sAT[(k + 3) * 128 + n] = v.w;
    }
    // ---- load W tile, transposed ----
#pragma unroll
    for (int it = 0; it < 8; it++) {
        int idx = it * 256 + t;
        int j = idx & 63, k4 = idx >> 6;    // k4: 0..31
        float4 v;
        if (xA0) v = ((const float4*)W0)[j * 32 + k4];
        else     v = (k4 < 16) ? ((const float4*)W0)[j * 16 + k4]
                               : ((const float4*)W1)[j * 16 + (k4 - 16)];
        int k = k4 * 4;
        sWT[(k + 0) * 64 + j] = v.x;
        sWT[(k + 1) * 64 + j] = v.y;
        sWT[(k + 2) * 64 + j] = v.z;
        sWT[(k + 3) * 64 + j] = v.w;
    }
    __syncthreads();

    // ---- main loop: thread tile 4 nodes x 8 outputs ----
    int tn = t & 31, tj = t >> 5;
    const float* aBase = sAT + tn * 4;
    const float* wBase = sWT + tj * 8;
    float acc[4][8];
#pragma unroll
    for (int i = 0; i < 4; i++)
#pragma unroll
        for (int j = 0; j < 8; j++) acc[i][j] = 0.f;

#pragma unroll 4
    for (int k = 0; k < 128; k++) {
        float4 a  = *(const float4*)(aBase + k * 128);
        float4 w0 = *(const float4*)(wBase + k * 64);
        float4 w1 = *(const float4*)(wBase + k * 64 + 4);
        float av[4] = {a.x, a.y, a.z, a.w};
        float wv[8] = {w0.x, w0.y, w0.z, w0.w, w1.x, w1.y, w1.z, w1.w};
#pragma unroll
        for (int i = 0; i < 4; i++)
#pragma unroll
            for (int j = 0; j < 8; j++) acc[i][j] = fmaf(av[i], wv[j], acc[i][j]);
    }

    // ---- add bias, stage results in smem ----
    float bv[8];
#pragma unroll
    for (int j = 0; j < 8; j++) bv[j] = __ldg(&bias[tj * 8 + j]);
    __syncthreads();
#pragma unroll
    for (int i = 0; i < 4; i++) {
        float4 lo = make_float4(acc[i][0] + bv[0], acc[i][1] + bv[1],
                                acc[i][2] + bv[2], acc[i][3] + bv[3]);
        float4 hi = make_float4(acc[i][4] + bv[4], acc[i][5] + bv[5],
                                acc[i][6] + bv[6], acc[i][7] + bv[7]);
        *(float4*)&sRes[(tn * 4 + i) * RES_PAD + tj * 8]     = lo;
        *(float4*)&sRes[(tn * 4 + i) * RES_PAD + tj * 8 + 4] = hi;
    }
    __syncthreads();

    // ---- epilogue: warp per 16 rows, lane covers 2 columns ----
    int w = t >> 5, lane = t & 31;
    float* oF = (mode == 2) ? outF : h32buf(outsel);
    __half2* oH = (__half2*)h16buf(outsel);
    float lg0 = 0.f, lg1 = 0.f, lb0 = 0.f, lb1 = 0.f;
    if (mode == 1) {
        lg0 = __ldg(&lng[lane * 2 + 0]);
        lg1 = __ldg(&lng[lane * 2 + 1]);
        lb0 = __ldg(&lnbeta[lane * 2 + 0]);
        lb1 = __ldg(&lnbeta[lane * 2 + 1]);
    }
    for (int r = 0; r < 16; r++) {
        int n = w * 16 + r;
        int gn = nb + n;
        if (gn >= N_NODES) break;
        float2 v = *(float2*)&sRes[n * RES_PAD + lane * 2];
        if (mode == 1) {
            float s = v.x + v.y;
            float sq = v.x * v.x + v.y * v.y;
#pragma unroll
            for (int off = 16; off; off >>= 1) {
                s  += __shfl_xor_sync(0xffffffffu, s, off);
                sq += __shfl_xor_sync(0xffffffffu, sq, off);
            }
            float mu = s * (1.0f / HID);
            float var = sq * (1.0f / HID) - mu * mu;
            float rs = rsqrtf(var + LN_EPS);
            v.x = fmaxf(fmaf(lg0, (v.x - mu) * rs, lb0), 0.f);
            v.y = fmaxf(fmaf(lg1, (v.y - mu) * rs, lb1), 0.f);
        } else if (mode == 0) {
            v.x = fmaxf(v.x, 0.f);
            v.y = fmaxf(v.y, 0.f);
        }
        ((float2*)oF)[(size_t)gn * 32 + lane] = v;
        if (mode != 2) oH[(size_t)gn * 32 + lane] = __float22half2_rn(v);
    }
}

// ---------------- launcher ---------------------------------------------------
extern "C" void kernel_launch(void* const* d_in, const int* in_sizes, int n_in,
                              void* d_out, int out_size) {
    const float* x     = (const float*)d_in[0];
    const int*   ei    = (const int*)d_in[1];
    const float* fcW   = (const float*)d_in[3];
    const float* fcb   = (const float*)d_in[4];
    const float* lin_l = (const float*)d_in[5];
    const float* lin_r = (const float*)d_in[6];
    const float* lin_b = (const float*)d_in[7];
    const float* ln_g  = (const float*)d_in[8];
    const float* ln_b  = (const float*)d_in[9];
    const int* src = ei;
    const int* dst = ei + N_EDGES;

    cudaFuncSetAttribute(k_gemm, cudaFuncAttributeMaxDynamicSharedMemorySize, GEMM_SMEM);

    k_zero_cnt<<<(N_NODES + 255) / 256, 256>>>();
    k_count<<<(N_EDGES + 255) / 256, 256>>>(dst);
    k_scan1<<<NCHUNK, 512>>>();
    k_scan2<<<1, 128>>>();
    k_scan3<<<(N_NODES + 255) / 256, 256>>>();
    k_scatter<<<(N_EDGES + 255) / 256, 256>>>(src, dst);

    int gblocks = (N_NODES + GB_NODES - 1) / GB_NODES;
    // fc: h0 = relu(x @ fcW^T + fcb) -> buffers 0
    k_gemm<<<gblocks, 256, GEMM_SMEM>>>(x, 0, fcW, nullptr, fcb,
                                        nullptr, nullptr, 0, 0, nullptr);

    int cur = 0;
    for (int l = 0; l < NUM_LAYERS; l++) {
        k_aggregate<<<(N_NODES * 32 + 255) / 256, 256>>>(cur);
        int mode = (l < NUM_LAYERS - 1) ? 1 : 2;
        k_gemm<<<gblocks, 256, GEMM_SMEM>>>(nullptr, cur,
                                            lin_l + l * HID * HID,
                                            lin_r + l * HID * HID,
                                            lin_b + l * HID,
                                            ln_g + l * HID, ln_b + l * HID,
                                            mode, 1 - cur, (float*)d_out);
        cur = 1 - cur;
    }
}

// round 4
// speedup vs baseline: 2.0478x; 1.2896x over previous
#include <cuda_runtime.h>
#include <cuda_fp16.h>
#include <cstdint>

#define N_NODES 50000
#define N_EDGES 1600000
#define IN_DIM 128
#define HID 64
#define NUM_LAYERS 3
#define LN_EPS 1e-5f
#define NCHUNK ((N_NODES + 511) / 512)

// HMMA GEMM: 128 rows x 64 cols per block, 256 threads (8 warps x 16 rows)
#define SA_STRIDE 136   // halfs per row (128 + 8 pad)
#define GEMM_SMEM ((2 * 128 * SA_STRIDE + 2 * 64 * SA_STRIDE) * 2)  // 104448 B

// ---------------- scratch (device globals) ----------------------------------
__device__ __half g_hiA[N_NODES * HID];
__device__ __half g_loA[N_NODES * HID];
__device__ __half g_hiB[N_NODES * HID];
__device__ __half g_loB[N_NODES * HID];
__device__ __half g_aggHi[N_NODES * HID];
__device__ __half g_aggLo[N_NODES * HID];
__device__ int    g_cnt[N_NODES];
__device__ int    g_excl[N_NODES];
__device__ int    g_row[N_NODES];
__device__ int    g_cur[N_NODES];
__device__ int    g_csum[128];
__device__ float  g_invdeg[N_NODES];
__device__ int    g_esrc[N_EDGES];

__device__ __forceinline__ __half* hibuf(int s) { return s == 0 ? g_hiA : g_hiB; }
__device__ __forceinline__ __half* lobuf(int s) { return s == 0 ? g_loA : g_loB; }

__device__ __forceinline__ uint32_t h2u(__half2 h) {
    return *reinterpret_cast<uint32_t*>(&h);
}
// split 8 fp32 into hi/lo fp16 packs
__device__ __forceinline__ void split8(const float* v, uint4& hi, uint4& lo) {
    __half h[8];
    __half l[8];
#pragma unroll
    for (int i = 0; i < 8; i++) {
        h[i] = __float2half_rn(v[i]);
        l[i] = __float2half_rn(v[i] - __half2float(h[i]));
    }
    hi.x = h2u(__halves2half2(h[0], h[1]));
    hi.y = h2u(__halves2half2(h[2], h[3]));
    hi.z = h2u(__halves2half2(h[4], h[5]));
    hi.w = h2u(__halves2half2(h[6], h[7]));
    lo.x = h2u(__halves2half2(l[0], l[1]));
    lo.y = h2u(__halves2half2(l[2], l[3]));
    lo.z = h2u(__halves2half2(l[4], l[5]));
    lo.w = h2u(__halves2half2(l[6], l[7]));
}

// ---------------- CSR construction -------------------------------------------
__global__ void k_zero_cnt() {
    int i = blockIdx.x * blockDim.x + threadIdx.x;
    if (i < N_NODES) g_cnt[i] = 0;
}

__global__ void k_count(const int* __restrict__ dst) {
    int e = blockIdx.x * blockDim.x + threadIdx.x;
    if (e < N_EDGES) atomicAdd(&g_cnt[dst[e]], 1);
}

__global__ void k_scan1() {
    __shared__ int s[512];
    int c = blockIdx.x, t = threadIdx.x, i = c * 512 + t;
    int v = (i < N_NODES) ? g_cnt[i] : 0;
    s[t] = v;
    __syncthreads();
    for (int off = 1; off < 512; off <<= 1) {
        int x = (t >= off) ? s[t - off] : 0;
        __syncthreads();
        s[t] += x;
        __syncthreads();
    }
    if (i < N_NODES) g_excl[i] = s[t] - v;
    if (t == 511) g_csum[c] = s[511];
}

__global__ void k_scan2() {
    __shared__ int s[128];
    int t = threadIdx.x;
    int v = (t < NCHUNK) ? g_csum[t] : 0;
    s[t] = v;
    __syncthreads();
    for (int off = 1; off < 128; off <<= 1) {
        int x = (t >= off) ? s[t - off] : 0;
        __syncthreads();
        s[t] += x;
        __syncthreads();
    }
    if (t < NCHUNK) g_csum[t] = s[t] - v;
}

__global__ void k_scan3() {
    int i = blockIdx.x * blockDim.x + threadIdx.x;
    if (i < N_NODES) {
        int r = g_excl[i] + g_csum[i >> 9];
        g_row[i] = r;
        g_cur[i] = r;
        int c = g_cnt[i];
        g_invdeg[i] = 1.0f / (float)(c > 0 ? c : 1);
    }
}

__global__ void k_scatter(const int* __restrict__ src, const int* __restrict__ dst) {
    int e = blockIdx.x * blockDim.x + threadIdx.x;
    if (e < N_EDGES) {
        int p = atomicAdd(&g_cur[dst[e]], 1);
        g_esrc[p] = src[e];
    }
}

// ---------------- mean aggregation (warp per dst node, fp16-hi gather) -------
__global__ void k_aggregate(int hsel) {
    int gw = (blockIdx.x * blockDim.x + threadIdx.x) >> 5;
    if (gw >= N_NODES) return;
    int lane = threadIdx.x & 31;
    const __half2* hp = (const __half2*)hibuf(hsel);
    int s = g_row[gw], c = g_cnt[gw];
    float ax = 0.f, ay = 0.f;
    int e = 0;
    for (; e + 4 <= c; e += 4) {
        int s0 = g_esrc[s + e + 0];
        int s1 = g_esrc[s + e + 1];
        int s2 = g_esrc[s + e + 2];
        int s3 = g_esrc[s + e + 3];
        float2 v0 = __half22float2(hp[(size_t)s0 * 32 + lane]);
        float2 v1 = __half22float2(hp[(size_t)s1 * 32 + lane]);
        float2 v2 = __half22float2(hp[(size_t)s2 * 32 + lane]);
        float2 v3 = __half22float2(hp[(size_t)s3 * 32 + lane]);
        ax += (v0.x + v1.x) + (v2.x + v3.x);
        ay += (v0.y + v1.y) + (v2.y + v3.y);
    }
    for (; e < c; e++) {
        float2 v0 = __half22float2(hp[(size_t)g_esrc[s + e] * 32 + lane]);
        ax += v0.x;
        ay += v0.y;
    }
    float id = g_invdeg[gw];
    float mx = ax * id, my = ay * id;
    __half hx = __float2half_rn(mx), hy = __float2half_rn(my);
    __half lx = __float2half_rn(mx - __half2float(hx));
    __half ly = __float2half_rn(my - __half2float(hy));
    ((__half2*)g_aggHi)[(size_t)gw * 32 + lane] = __halves2half2(hx, hy);
    ((__half2*)g_aggLo)[(size_t)gw * 32 + lane] = __halves2half2(lx, ly);
}

// ---------------- split-fp16 HMMA GEMM ---------------------------------------
// out[128n][64j] = A[128n][128k] @ W[64j][128k]^T, fp32-equivalent precision
// xA0 != null : A = xA0 fp32 (split on the fly), B = W0 fp32 [64][128]  (fc)
// xA0 == null : A = [agg | h(hsel)] (pre-split), B = [W0 | W1] [64][64] each
// mode: 0 = ReLU -> h(outsel); 1 = LN+ReLU -> h(outsel); 2 = raw -> outF
__global__ void k_gemm(const float* __restrict__ xA0, int hsel,
                       const float* __restrict__ W0, const float* __restrict__ W1,
                       const float* __restrict__ bias,
                       const float* __restrict__ lng, const float* __restrict__ lnbeta,
                       int mode, int outsel, float* __restrict__ outF) {
    extern __shared__ __half sm[];
    __half* sAh = sm;                        // [128][SA_STRIDE]
    __half* sAl = sm + 128 * SA_STRIDE;
    __half* sBh = sm + 2 * 128 * SA_STRIDE;  // [64][SA_STRIDE]
    __half* sBl = sBh + 64 * SA_STRIDE;

    int t = threadIdx.x;
    int nb = blockIdx.x * 128;
    const __half* hHi = hibuf(hsel);
    const __half* hLo = lobuf(hsel);

    // ---- stage A tile ----
#pragma unroll
    for (int it = 0; it < 8; it++) {
        int idx = it * 256 + t;            // 2048 uint4 slots
        int n = idx >> 4, k8 = idx & 15;
        int gn = nb + n;
        uint4 dh = make_uint4(0u, 0u, 0u, 0u), dl = dh;
        if (gn < N_NODES) {
            if (xA0) {
                float v[8];
                *(float4*)&v[0] = ((const float4*)xA0)[(size_t)gn * 32 + k8 * 2];
                *(float4*)&v[4] = ((const float4*)xA0)[(size_t)gn * 32 + k8 * 2 + 1];
                split8(v, dh, dl);
            } else if (k8 < 8) {
                dh = ((const uint4*)g_aggHi)[(size_t)gn * 8 + k8];
                dl = ((const uint4*)g_aggLo)[(size_t)gn * 8 + k8];
            } else {
                dh = ((const uint4*)hHi)[(size_t)gn * 8 + (k8 - 8)];
                dl = ((const uint4*)hLo)[(size_t)gn * 8 + (k8 - 8)];
            }
        }
        *(uint4*)&sAh[n * SA_STRIDE + k8 * 8] = dh;
        *(uint4*)&sAl[n * SA_STRIDE + k8 * 8] = dl;
    }
    // ---- stage B tile (weights fp32 -> hi/lo fp16) ----
#pragma unroll
    for (int it = 0; it < 4; it++) {
        int idx = it * 256 + t;            // 1024 uint4 slots
        int j = idx >> 4, k8 = idx & 15;
        float v[8];
        if (xA0) {
            *(float4*)&v[0] = ((const float4*)W0)[j * 32 + k8 * 2];
            *(float4*)&v[4] = ((const float4*)W0)[j * 32 + k8 * 2 + 1];
        } else if (k8 < 8) {
            *(float4*)&v[0] = ((const float4*)W0)[j * 16 + k8 * 2];
            *(float4*)&v[4] = ((const float4*)W0)[j * 16 + k8 * 2 + 1];
        } else {
            *(float4*)&v[0] = ((const float4*)W1)[j * 16 + (k8 - 8) * 2];
            *(float4*)&v[4] = ((const float4*)W1)[j * 16 + (k8 - 8) * 2 + 1];
        }
        uint4 dh, dl;
        split8(v, dh, dl);
        *(uint4*)&sBh[j * SA_STRIDE + k8 * 8] = dh;
        *(uint4*)&sBl[j * SA_STRIDE + k8 * 8] = dl;
    }
    __syncthreads();

    int warp = t >> 5, lane = t & 31;
    int wm = warp * 16;

    float acc[8][4];
#pragma unroll
    for (int p = 0; p < 8; p++)
#pragma unroll
        for (int q = 0; q < 4; q++) acc[p][q] = 0.f;

    uint32_t aOff = (uint32_t)((wm + (lane & 15)) * SA_STRIDE + (lane >> 4) * 8) * 2;
    uint32_t aShH = (uint32_t)__cvta_generic_to_shared(sAh) + aOff;
    uint32_t aShL = (uint32_t)__cvta_generic_to_shared(sAl) + aOff;
    int ng = lane >> 3;                         // 0..3
    int bRow = ((ng >> 1) * 8) + (lane & 7);    // n within 16-group
    int bK = (ng & 1) * 8;                      // k half
    uint32_t bShH = (uint32_t)__cvta_generic_to_shared(sBh);
    uint32_t bShL = (uint32_t)__cvta_generic_to_shared(sBl);

#define LDM(r0, r1, r2, r3, addr) \
    asm volatile("ldmatrix.sync.aligned.m8n8.x4.shared.b16 {%0,%1,%2,%3}, [%4];" \
                 : "=r"(r0), "=r"(r1), "=r"(r2), "=r"(r3) : "r"(addr))
#define MMA(accp, x0, x1, x2, x3, y0, y1) \
    asm volatile("mma.sync.aligned.m16n8k16.row.col.f32.f16.f16.f32 " \
                 "{%0,%1,%2,%3}, {%4,%5,%6,%7}, {%8,%9}, {%0,%1,%2,%3};" \
                 : "+f"(accp[0]), "+f"(accp[1]), "+f"(accp[2]), "+f"(accp[3]) \
                 : "r"(x0), "r"(x1), "r"(x2), "r"(x3), "r"(y0), "r"(y1))

#pragma unroll
    for (int kk = 0; kk < 8; kk++) {
        uint32_t ah0, ah1, ah2, ah3, al0, al1, al2, al3;
        LDM(ah0, ah1, ah2, ah3, aShH + kk * 32);
        LDM(al0, al1, al2, al3, aShL + kk * 32);
#pragma unroll
        for (int tp = 0; tp < 4; tp++) {
            uint32_t bOff = (uint32_t)((tp * 16 + bRow) * SA_STRIDE + kk * 16 + bK) * 2;
            uint32_t bh0, bh1, bh2, bh3, bl0, bl1, bl2, bl3;
            LDM(bh0, bh1, bh2, bh3, bShH + bOff);
            LDM(bl0, bl1, bl2, bl3, bShL + bOff);
            MMA(acc[2 * tp],     ah0, ah1, ah2, ah3, bh0, bh1);
            MMA(acc[2 * tp],     ah0, ah1, ah2, ah3, bl0, bl1);
            MMA(acc[2 * tp],     al0, al1, al2, al3, bh0, bh1);
            MMA(acc[2 * tp + 1], ah0, ah1, ah2, ah3, bh2, bh3);
            MMA(acc[2 * tp + 1], ah0, ah1, ah2, ah3, bl2, bl3);
            MMA(acc[2 * tp + 1], al0, al1, al2, al3, bh2, bh3);
        }
    }
#undef LDM
#undef MMA

    // ---- epilogue: bias (+LN) (+ReLU), write from registers ----
    int r = lane >> 2, cc = (lane & 3) * 2;     // rows wm+r, wm+r+8; cols p*8+cc
#pragma unroll
    for (int p = 0; p < 8; p++) {
        float b0 = __ldg(&bias[p * 8 + cc]);
        float b1 = __ldg(&bias[p * 8 + cc + 1]);
        acc[p][0] += b0; acc[p][1] += b1;
        acc[p][2] += b0; acc[p][3] += b1;
    }
    if (mode == 1) {
        float s0 = 0.f, q0 = 0.f, s1 = 0.f, q1 = 0.f;
#pragma unroll
        for (int p = 0; p < 8; p++) {
            s0 += acc[p][0] + acc[p][1];
            q0 += acc[p][0] * acc[p][0] + acc[p][1] * acc[p][1];
            s1 += acc[p][2] + acc[p][3];
            q1 += acc[p][2] * acc[p][2] + acc[p][3] * acc[p][3];
        }
#pragma unroll
        for (int off = 1; off < 4; off <<= 1) {
            s0 += __shfl_xor_sync(0xffffffffu, s0, off);
            q0 += __shfl_xor_sync(0xffffffffu, q0, off);
            s1 += __shfl_xor_sync(0xffffffffu, s1, off);
            q1 += __shfl_xor_sync(0xffffffffu, q1, off);
        }
        float mu0 = s0 * (1.0f / HID), mu1 = s1 * (1.0f / HID);
        float rs0 = rsqrtf(q0 * (1.0f / HID) - mu0 * mu0 + LN_EPS);
        float rs1 = rsqrtf(q1 * (1.0f / HID) - mu1 * mu1 + LN_EPS);
#pragma unroll
        for (int p = 0; p < 8; p++) {
            float g0 = __ldg(&lng[p * 8 + cc]);
            float g1 = __ldg(&lng[p * 8 + cc + 1]);
            float t0 = __ldg(&lnbeta[p * 8 + cc]);
            float t1 = __ldg(&lnbeta[p * 8 + cc + 1]);
            acc[p][0] = fmaxf(fmaf(g0, (acc[p][0] - mu0) * rs0, t0), 0.f);
            acc[p][1] = fmaxf(fmaf(g1, (acc[p][1] - mu0) * rs0, t1), 0.f);
            acc[p][2] = fmaxf(fmaf(g0, (acc[p][2] - mu1) * rs1, t0), 0.f);
            acc[p][3] = fmaxf(fmaf(g1, (acc[p][3] - mu1) * rs1, t1), 0.f);
        }
    } else if (mode == 0) {
#pragma unroll
        for (int p = 0; p < 8; p++)
#pragma unroll
            for (int q = 0; q < 4; q++) acc[p][q] = fmaxf(acc[p][q], 0.f);
    }

    int gn0 = nb + wm + r, gn1 = gn0 + 8;
    if (mode == 2) {
#pragma unroll
        for (int p = 0; p < 8; p++) {
            int ci = p * 4 + (lane & 3);
            if (gn0 < N_NODES)
                ((float2*)outF)[(size_t)gn0 * 32 + ci] = make_float2(acc[p][0], acc[p][1]);
            if (gn1 < N_NODES)
                ((float2*)outF)[(size_t)gn1 * 32 + ci] = make_float2(acc[p][2], acc[p][3]);
        }
    } else {
        __half2* oHi = (__half2*)hibuf(outsel);
        __half2* oLo = (__half2*)lobuf(outsel);
#pragma unroll
        for (int p = 0; p < 8; p++) {
            int ci = p * 4 + (lane & 3);
            if (gn0 < N_NODES) {
                __half h0 = __float2half_rn(acc[p][0]);
                __half h1 = __float2half_rn(acc[p][1]);
                oHi[(size_t)gn0 * 32 + ci] = __halves2half2(h0, h1);
                oLo[(size_t)gn0 * 32 + ci] = __halves2half2(
                    __float2half_rn(acc[p][0] - __half2float(h0)),
                    __float2half_rn(acc[p][1] - __half2float(h1)));
            }
            if (gn1 < N_NODES) {
                __half h2 = __float2half_rn(acc[p][2]);
                __half h3 = __float2half_rn(acc[p][3]);
                oHi[(size_t)gn1 * 32 + ci] = __halves2half2(h2, h3);
                oLo[(size_t)gn1 * 32 + ci] = __halves2half2(
                    __float2half_rn(acc[p][2] - __half2float(h2)),
                    __float2half_rn(acc[p][3] - __half2float(h3)));
            }
        }
    }
}

// ---------------- launcher ---------------------------------------------------
extern "C" void kernel_launch(void* const* d_in, const int* in_sizes, int n_in,
                              void* d_out, int out_size) {
    const float* x     = (const float*)d_in[0];
    const int*   ei    = (const int*)d_in[1];
    const float* fcW   = (const float*)d_in[3];
    const float* fcb   = (const float*)d_in[4];
    const float* lin_l = (const float*)d_in[5];
    const float* lin_r = (const float*)d_in[6];
    const float* lin_b = (const float*)d_in[7];
    const float* ln_g  = (const float*)d_in[8];
    const float* ln_b  = (const float*)d_in[9];
    const int* src = ei;
    const int* dst = ei + N_EDGES;

    cudaFuncSetAttribute(k_gemm, cudaFuncAttributeMaxDynamicSharedMemorySize, GEMM_SMEM);

    k_zero_cnt<<<(N_NODES + 255) / 256, 256>>>();
    k_count<<<(N_EDGES + 255) / 256, 256>>>(dst);
    k_scan1<<<NCHUNK, 512>>>();
    k_scan2<<<1, 128>>>();
    k_scan3<<<(N_NODES + 255) / 256, 256>>>();
    k_scatter<<<(N_EDGES + 255) / 256, 256>>>(src, dst);

    int gblocks = (N_NODES + 127) / 128;
    // fc: h0 = relu(x @ fcW^T + fcb) -> hi/lo buffer 0
    k_gemm<<<gblocks, 256, GEMM_SMEM>>>(x, 0, fcW, nullptr, fcb,
                                        nullptr, nullptr, 0, 0, nullptr);

    int cur = 0;
    for (int l = 0; l < NUM_LAYERS; l++) {
        k_aggregate<<<(N_NODES * 32 + 255) / 256, 256>>>(cur);
        int mode = (l < NUM_LAYERS - 1) ? 1 : 2;
        k_gemm<<<gblocks, 256, GEMM_SMEM>>>(nullptr, cur,
                                            lin_l + l * HID * HID,
                                            lin_r + l * HID * HID,
                                            lin_b + l * HID,
                                            ln_g + l * HID, ln_b + l * HID,
                                            mode, 1 - cur, (float*)d_out);
        cur = 1 - cur;
    }
}